// round 3
// baseline (speedup 1.0000x reference)
#include <cuda_runtime.h>

// ---------------------------------------------------------------------------
// Seq2seq LSTM: encoder (48 steps, C_IN=16) -> decoder (24 steps, zero input)
// -> per-timestep dense H->8.  N=8192, H=256, 4H=1024.
//
// Batch-parallel persistent CTAs: 128 CTAs x 512 threads, 64 samples/CTA,
// h double-buffered + c in SMEM. Weights pre-transposed AND pre-duplicated
// ((w,w) pairs) so one LDG.64 feeds fma.rn.f32x2 directly. Weight loads are
// software-pipelined (register double buffer, prefetch distance 1) to hide
// L2 latency (L1 is eaten by the SMEM carveout).
// ---------------------------------------------------------------------------

#define T_IN   48
#define T_OUT  24
#define C_IN   16
#define C_OUT  8
#define HID    256
#define H4     1024
#define NBATCH 8192

#define NXT (T_IN * C_IN * NBATCH)      // transposed x: [t][c][n]

typedef unsigned long long ULL;

__device__ float g_xT[NXT];                    // ~25 MB scratch
__device__ ULL   g_WihT2[(C_IN + 1) * H4];     // duplicated pairs, +1 pad row
__device__ ULL   g_WhhTe2[(HID + 1) * H4];     // duplicated pairs, +1 pad row
__device__ ULL   g_WhhTd2[(HID + 1) * H4];     // duplicated pairs, +1 pad row

// ---- packed f32x2 helpers --------------------------------------------------
__device__ __forceinline__ ULL dup2(float w) {
    ULL r; unsigned u = __float_as_uint(w);
    asm("mov.b64 %0, {%1, %2};" : "=l"(r) : "r"(u), "r"(u));
    return r;
}
__device__ __forceinline__ float2 upk(ULL v) {
    unsigned lo, hi;
    asm("mov.b64 {%0, %1}, %2;" : "=r"(lo), "=r"(hi) : "l"(v));
    return make_float2(__uint_as_float(lo), __uint_as_float(hi));
}
__device__ __forceinline__ ULL f2(ULL a, ULL b, ULL c) {
    ULL d;
    asm("fma.rn.f32x2 %0, %1, %2, %3;" : "=l"(d) : "l"(a), "l"(b), "l"(c));
    return d;
}

// ---- activations -------------------------------------------------------------
__device__ __forceinline__ float sigf(float x) {
    return __fdividef(1.0f, 1.0f + __expf(-x));
}
__device__ __forceinline__ float tanh_(float x) {
    return 1.0f - __fdividef(2.0f, __expf(2.0f * x) + 1.0f);
}

// ---- layout constants ---------------------------------------------------------
constexpr int HS    = 68;           // padded SMEM row stride (16B aligned)
constexpr int HBUF  = HID * HS;     // 17408 floats per h/c buffer
constexpr int SMEM_FLOATS = 3 * HBUF + 2 * C_IN * 64;   // + x ping-pong
constexpr int SMEM_BYTES  = SMEM_FLOATS * 4;            // 217088 B

// ---------------------------------------------------------------------------
// Prep: transpose x; transpose + duplicate the weights.
// ---------------------------------------------------------------------------
__global__ void prep_kernel(const float* __restrict__ x,
                            const float* __restrict__ Wih,
                            const float* __restrict__ Whhe,
                            const float* __restrict__ Whhd)
{
    const int B1 = NXT;
    const int B2 = B1 + 2 * C_IN * H4;
    const int B3 = B2 + 2 * HID * H4;
    const int TOTAL = B3 + 2 * HID * H4;
    for (int i = blockIdx.x * blockDim.x + threadIdx.x; i < TOTAL;
         i += gridDim.x * blockDim.x) {
        if (i < B1) {
            int t = i / (C_IN * NBATCH);
            int r = i - t * (C_IN * NBATCH);
            int c = r >> 13;            // / 8192
            int n = r & 8191;
            g_xT[i] = x[(n * C_IN + c) * T_IN + t];
        } else if (i < B2) {
            int j = i - B1, p = j >> 1;
            int c = p >> 10, col = p & 1023;
            ((float*)g_WihT2)[j] = Wih[col * C_IN + c];
        } else if (i < B3) {
            int j = i - B2, p = j >> 1;
            int k = p >> 10, col = p & 1023;
            ((float*)g_WhhTe2)[j] = Whhe[col * HID + k];
        } else {
            int j = i - B3, p = j >> 1;
            int k = p >> 10, col = p & 1023;
            ((float*)g_WhhTd2)[j] = Whhd[col * HID + k];
        }
    }
}

// 8 packed FMAs for one gate row against 4 ulonglong2 (16 samples)
#define FMA8(g, q)                                                          \
    acc[g][0] = f2(q, p0.x, acc[g][0]); acc[g][1] = f2(q, p0.y, acc[g][1]); \
    acc[g][2] = f2(q, p1.x, acc[g][2]); acc[g][3] = f2(q, p1.y, acc[g][3]); \
    acc[g][4] = f2(q, p2.x, acc[g][4]); acc[g][5] = f2(q, p2.y, acc[g][5]); \
    acc[g][6] = f2(q, p3.x, acc[g][6]); acc[g][7] = f2(q, p3.y, acc[g][7]);

// ---------------------------------------------------------------------------
// One LSTM half-pass: gates for hidden index k_h, samples [bn, bn+16).
// Weight loads are pipelined (prefetch distance 1; arrays have a pad row so
// the last prefetch stays in-bounds).
// ---------------------------------------------------------------------------
template <bool WITH_X>
__device__ __forceinline__ void lstm_pass(
    const ULL* __restrict__ wh,      // duplicated transposed Whh [k][col]
    ULL bi, ULL bf, ULL bg, ULL bo,
    const float* __restrict__ hcur, float* __restrict__ hnxt,
    float* __restrict__ cs, const float* __restrict__ xs,
    int k_h, int bn)
{
    ULL acc[4][8];
    #pragma unroll
    for (int i = 0; i < 8; ++i) {
        acc[0][i] = bi; acc[1][i] = bf; acc[2][i] = bg; acc[3][i] = bo;
    }

    if (WITH_X) {
        const ULL* wr = g_WihT2 + k_h;
        const float* xr = xs + bn;
        ULL n0 = wr[0], n1 = wr[256], n2 = wr[512], n3 = wr[768];
        #pragma unroll
        for (int c = 0; c < C_IN; ++c) {
            ULL q0 = n0, q1 = n1, q2 = n2, q3 = n3;
            wr += H4;                          // last iter reads pad row
            n0 = wr[0]; n1 = wr[256]; n2 = wr[512]; n3 = wr[768];
            const ulonglong2* xp = reinterpret_cast<const ulonglong2*>(xr);
            ulonglong2 p0 = xp[0], p1 = xp[1], p2 = xp[2], p3 = xp[3];
            FMA8(0, q0) FMA8(1, q1) FMA8(2, q2) FMA8(3, q3)
            xr += 64;
        }
    }

    {
        const ULL* wr = wh + k_h;
        const float* hr = hcur + bn;
        ULL n0 = wr[0], n1 = wr[256], n2 = wr[512], n3 = wr[768];
        #pragma unroll 2
        for (int k = 0; k < HID; ++k) {
            ULL q0 = n0, q1 = n1, q2 = n2, q3 = n3;
            wr += H4;                          // last iter reads pad row
            n0 = wr[0]; n1 = wr[256]; n2 = wr[512]; n3 = wr[768];
            const ulonglong2* hp = reinterpret_cast<const ulonglong2*>(hr);
            ulonglong2 p0 = hp[0], p1 = hp[1], p2 = hp[2], p3 = hp[3];
            FMA8(0, q0) FMA8(1, q1) FMA8(2, q2) FMA8(3, q3)
            hr += HS;
        }
    }

    // elementwise LSTM update (this thread exclusively owns (k_h, n) cells)
    #pragma unroll
    for (int i = 0; i < 8; ++i) {
        float2 vi = upk(acc[0][i]), vf = upk(acc[1][i]);
        float2 vg = upk(acc[2][i]), vo = upk(acc[3][i]);
        int idx = k_h * HS + bn + 2 * i;
        {
            float co = cs[idx];
            float cn = sigf(vf.x) * co + sigf(vi.x) * tanh_(vg.x);
            cs[idx]   = cn;
            hnxt[idx] = sigf(vo.x) * tanh_(cn);
        }
        {
            float co = cs[idx + 1];
            float cn = sigf(vf.y) * co + sigf(vi.y) * tanh_(vg.y);
            cs[idx + 1]   = cn;
            hnxt[idx + 1] = sigf(vo.y) * tanh_(cn);
        }
    }
}

// ---------------------------------------------------------------------------
// Main persistent kernel: 128 CTAs x 512 threads, 64 samples per CTA.
// ---------------------------------------------------------------------------
__global__ void __launch_bounds__(512, 1)
lstm_kernel(const float* __restrict__ enc_b, const float* __restrict__ dec_b,
            const float* __restrict__ dense_W, const float* __restrict__ dense_b,
            float* __restrict__ out)
{
    extern __shared__ float smem[];
    float* hA  = smem;
    float* hB  = smem + HBUF;
    float* cs  = smem + 2 * HBUF;
    float* xsA = smem + 3 * HBUF;
    float* xsB = xsA + C_IN * 64;

    const int tid = threadIdx.x;
    const int k_h = tid & 255;
    const int nh  = tid >> 8;          // 0 or 1: sample half
    const int n0  = blockIdx.x * 64;

    // zero h (current) and c; hB is fully overwritten before first read
    for (int i = tid; i < HBUF; i += 512) { hA[i] = 0.0f; cs[i] = 0.0f; }
    // preload x tile for t=0
    for (int i = tid; i < C_IN * 64; i += 512)
        xsA[i] = g_xT[(i >> 6) * NBATCH + n0 + (i & 63)];
    __syncthreads();

    float* hcur = hA;
    float* hnxt = hB;

    // -------- encoder --------
    {
        ULL bi = dup2(enc_b[k_h]),       bf = dup2(enc_b[256 + k_h]);
        ULL bg = dup2(enc_b[512 + k_h]), bo = dup2(enc_b[768 + k_h]);
        for (int t = 0; t < T_IN; ++t) {
            lstm_pass<true>(g_WhhTe2, bi, bf, bg, bo, hcur, hnxt, cs, xsA,
                            k_h, nh * 32);
            lstm_pass<true>(g_WhhTe2, bi, bf, bg, bo, hcur, hnxt, cs, xsA,
                            k_h, nh * 32 + 16);
            if (t + 1 < T_IN) {
                for (int i = tid; i < C_IN * 64; i += 512)
                    xsB[i] = g_xT[((t + 1) * C_IN + (i >> 6)) * NBATCH
                                  + n0 + (i & 63)];
            }
            __syncthreads();
            float* tp = hcur; hcur = hnxt; hnxt = tp;
            tp = xsA; xsA = xsB; xsB = tp;
        }
    }

    // decoder starts from (h_enc, c = 0)
    for (int i = tid; i < HBUF; i += 512) cs[i] = 0.0f;
    __syncthreads();

    // -------- decoder + per-timestep dense --------
    const int nl = tid & 63;
    const int oo = tid >> 6;           // 0..7
    {
        ULL bi = dup2(dec_b[k_h]),       bf = dup2(dec_b[256 + k_h]);
        ULL bg = dup2(dec_b[512 + k_h]), bo = dup2(dec_b[768 + k_h]);
        for (int t = 0; t < T_OUT; ++t) {
            lstm_pass<false>(g_WhhTd2, bi, bf, bg, bo, hcur, hnxt, cs, nullptr,
                             k_h, nh * 32);
            lstm_pass<false>(g_WhhTd2, bi, bf, bg, bo, hcur, hnxt, cs, nullptr,
                             k_h, nh * 32 + 16);
            __syncthreads();
            float* tp = hcur; hcur = hnxt; hnxt = tp;

            // dense: out[n][o][t] = b[t][o] + sum_k h[n][k] * W[t][o][k]
            // dw is warp-uniform (broadcast LDG.128); hr is conflict-free LDS.
            const float4* dw = reinterpret_cast<const float4*>(
                dense_W + (t * C_OUT + oo) * HID);
            const float* hr = hcur + nl;
            float a = __ldg(dense_b + t * C_OUT + oo);
            #pragma unroll 4
            for (int k4 = 0; k4 < HID / 4; ++k4) {
                float4 w = __ldg(dw + k4);
                a = fmaf(hr[(4 * k4 + 0) * HS], w.x, a);
                a = fmaf(hr[(4 * k4 + 1) * HS], w.y, a);
                a = fmaf(hr[(4 * k4 + 2) * HS], w.z, a);
                a = fmaf(hr[(4 * k4 + 3) * HS], w.w, a);
            }
            out[((size_t)(n0 + nl) * C_OUT + oo) * T_OUT + t] = a;
            // no sync needed: next step writes the other h buffer; this one is
            // only rewritten after the next step's end-of-step barrier.
        }
    }
}

#undef FMA8

// ---------------------------------------------------------------------------
extern "C" void kernel_launch(void* const* d_in, const int* in_sizes, int n_in,
                              void* d_out, int out_size)
{
    (void)in_sizes; (void)n_in; (void)out_size;
    const float* x        = (const float*)d_in[0];
    const float* enc_Wih  = (const float*)d_in[1];
    const float* enc_Whh  = (const float*)d_in[2];
    const float* enc_b    = (const float*)d_in[3];
    const float* dec_Whh  = (const float*)d_in[4];
    const float* dec_b    = (const float*)d_in[5];
    const float* dense_W  = (const float*)d_in[6];
    const float* dense_b  = (const float*)d_in[7];
    float* out = (float*)d_out;

    cudaFuncSetAttribute(lstm_kernel,
                         cudaFuncAttributeMaxDynamicSharedMemorySize, SMEM_BYTES);

    prep_kernel<<<1024, 512>>>(x, enc_Wih, enc_Whh, dec_Whh);
    lstm_kernel<<<128, 512, SMEM_BYTES>>>(enc_b, dec_b, dense_W, dense_b, out);
}

// round 4
// speedup vs baseline: 1.0550x; 1.0550x over previous
#include <cuda_runtime.h>

// ---------------------------------------------------------------------------
// Seq2seq LSTM: encoder (48 steps, C_IN=16) -> decoder (24 steps, zero input)
// -> per-timestep dense H->8.  N=8192, H=256, 4H=1024.
//
// Batch-parallel persistent CTAs: 128 CTAs x 512 threads, 64 samples/CTA,
// h double-buffered + c in SMEM. Weights pre-transposed AND pre-duplicated
// ((w,w) pairs) so one LDG.64 feeds fma.rn.f32x2 directly. Weight loads are
// software-pipelined (register double buffer, prefetch distance 1) to hide
// L2 latency (L1 is eaten by the SMEM carveout).
// ---------------------------------------------------------------------------

#define T_IN   48
#define T_OUT  24
#define C_IN   16
#define C_OUT  8
#define HID    256
#define H4     1024
#define NBATCH 8192

#define NXT (T_IN * C_IN * NBATCH)      // transposed x: [t][c][n]

typedef unsigned long long ULL;

__device__ float g_xT[NXT];                    // ~25 MB scratch
__device__ ULL   g_WihT2[(C_IN + 1) * H4];     // duplicated pairs, +1 pad row
__device__ ULL   g_WhhTe2[(HID + 1) * H4];     // duplicated pairs, +1 pad row
__device__ ULL   g_WhhTd2[(HID + 1) * H4];     // duplicated pairs, +1 pad row

// ---- packed f32x2 helpers --------------------------------------------------
__device__ __forceinline__ ULL dup2(float w) {
    ULL r; unsigned u = __float_as_uint(w);
    asm("mov.b64 %0, {%1, %2};" : "=l"(r) : "r"(u), "r"(u));
    return r;
}
__device__ __forceinline__ float2 upk(ULL v) {
    unsigned lo, hi;
    asm("mov.b64 {%0, %1}, %2;" : "=r"(lo), "=r"(hi) : "l"(v));
    return make_float2(__uint_as_float(lo), __uint_as_float(hi));
}
__device__ __forceinline__ ULL f2(ULL a, ULL b, ULL c) {
    ULL d;
    asm("fma.rn.f32x2 %0, %1, %2, %3;" : "=l"(d) : "l"(a), "l"(b), "l"(c));
    return d;
}

// ---- activations -------------------------------------------------------------
__device__ __forceinline__ float sigf(float x) {
    return __fdividef(1.0f, 1.0f + __expf(-x));
}
__device__ __forceinline__ float tanh_(float x) {
    return 1.0f - __fdividef(2.0f, __expf(2.0f * x) + 1.0f);
}

// ---- layout constants ---------------------------------------------------------
constexpr int HS    = 68;           // padded SMEM row stride (16B aligned)
constexpr int HBUF  = HID * HS;     // 17408 floats per h/c buffer
constexpr int SMEM_FLOATS = 3 * HBUF + 2 * C_IN * 64;   // + x ping-pong
constexpr int SMEM_BYTES  = SMEM_FLOATS * 4;            // 217088 B

// ---------------------------------------------------------------------------
// Prep: transpose x; transpose + duplicate the weights.
// ---------------------------------------------------------------------------
__global__ void prep_kernel(const float* __restrict__ x,
                            const float* __restrict__ Wih,
                            const float* __restrict__ Whhe,
                            const float* __restrict__ Whhd)
{
    const int B1 = NXT;
    const int B2 = B1 + 2 * C_IN * H4;
    const int B3 = B2 + 2 * HID * H4;
    const int TOTAL = B3 + 2 * HID * H4;
    for (int i = blockIdx.x * blockDim.x + threadIdx.x; i < TOTAL;
         i += gridDim.x * blockDim.x) {
        if (i < B1) {
            int t = i / (C_IN * NBATCH);
            int r = i - t * (C_IN * NBATCH);
            int c = r >> 13;            // / 8192
            int n = r & 8191;
            g_xT[i] = x[(n * C_IN + c) * T_IN + t];
        } else if (i < B2) {
            int j = i - B1, p = j >> 1;
            int c = p >> 10, col = p & 1023;
            ((float*)g_WihT2)[j] = Wih[col * C_IN + c];
        } else if (i < B3) {
            int j = i - B2, p = j >> 1;
            int k = p >> 10, col = p & 1023;
            ((float*)g_WhhTe2)[j] = Whhe[col * HID + k];
        } else {
            int j = i - B3, p = j >> 1;
            int k = p >> 10, col = p & 1023;
            ((float*)g_WhhTd2)[j] = Whhd[col * HID + k];
        }
    }
}

// 8 packed FMAs for one gate row against 4 ulonglong2 (16 samples)
#define FMA8(g, q)                                                          \
    acc[g][0] = f2(q, p0.x, acc[g][0]); acc[g][1] = f2(q, p0.y, acc[g][1]); \
    acc[g][2] = f2(q, p1.x, acc[g][2]); acc[g][3] = f2(q, p1.y, acc[g][3]); \
    acc[g][4] = f2(q, p2.x, acc[g][4]); acc[g][5] = f2(q, p2.y, acc[g][5]); \
    acc[g][6] = f2(q, p3.x, acc[g][6]); acc[g][7] = f2(q, p3.y, acc[g][7]);

// ---------------------------------------------------------------------------
// One LSTM half-pass: gates for hidden index k_h, samples [bn, bn+16).
// Weight loads are pipelined (prefetch distance 1; arrays have a pad row so
// the last prefetch stays in-bounds).
// ---------------------------------------------------------------------------
template <bool WITH_X>
__device__ __forceinline__ void lstm_pass(
    const ULL* __restrict__ wh,      // duplicated transposed Whh [k][col]
    ULL bi, ULL bf, ULL bg, ULL bo,
    const float* __restrict__ hcur, float* __restrict__ hnxt,
    float* __restrict__ cs, const float* __restrict__ xs,
    int k_h, int bn)
{
    ULL acc[4][8];
    #pragma unroll
    for (int i = 0; i < 8; ++i) {
        acc[0][i] = bi; acc[1][i] = bf; acc[2][i] = bg; acc[3][i] = bo;
    }

    if (WITH_X) {
        const ULL* wr = g_WihT2 + k_h;
        const float* xr = xs + bn;
        ULL n0 = wr[0], n1 = wr[256], n2 = wr[512], n3 = wr[768];
        #pragma unroll
        for (int c = 0; c < C_IN; ++c) {
            ULL q0 = n0, q1 = n1, q2 = n2, q3 = n3;
            wr += H4;                          // last iter reads pad row
            n0 = wr[0]; n1 = wr[256]; n2 = wr[512]; n3 = wr[768];
            const ulonglong2* xp = reinterpret_cast<const ulonglong2*>(xr);
            ulonglong2 p0 = xp[0], p1 = xp[1], p2 = xp[2], p3 = xp[3];
            FMA8(0, q0) FMA8(1, q1) FMA8(2, q2) FMA8(3, q3)
            xr += 64;
        }
    }

    {
        const ULL* wr = wh + k_h;
        const float* hr = hcur + bn;
        ULL n0 = wr[0], n1 = wr[256], n2 = wr[512], n3 = wr[768];
        #pragma unroll 2
        for (int k = 0; k < HID; ++k) {
            ULL q0 = n0, q1 = n1, q2 = n2, q3 = n3;
            wr += H4;                          // last iter reads pad row
            n0 = wr[0]; n1 = wr[256]; n2 = wr[512]; n3 = wr[768];
            const ulonglong2* hp = reinterpret_cast<const ulonglong2*>(hr);
            ulonglong2 p0 = hp[0], p1 = hp[1], p2 = hp[2], p3 = hp[3];
            FMA8(0, q0) FMA8(1, q1) FMA8(2, q2) FMA8(3, q3)
            hr += HS;
        }
    }

    // elementwise LSTM update (this thread exclusively owns (k_h, n) cells)
    #pragma unroll
    for (int i = 0; i < 8; ++i) {
        float2 vi = upk(acc[0][i]), vf = upk(acc[1][i]);
        float2 vg = upk(acc[2][i]), vo = upk(acc[3][i]);
        int idx = k_h * HS + bn + 2 * i;
        {
            float co = cs[idx];
            float cn = sigf(vf.x) * co + sigf(vi.x) * tanh_(vg.x);
            cs[idx]   = cn;
            hnxt[idx] = sigf(vo.x) * tanh_(cn);
        }
        {
            float co = cs[idx + 1];
            float cn = sigf(vf.y) * co + sigf(vi.y) * tanh_(vg.y);
            cs[idx + 1]   = cn;
            hnxt[idx + 1] = sigf(vo.y) * tanh_(cn);
        }
    }
}

// ---------------------------------------------------------------------------
// Main persistent kernel: 128 CTAs x 512 threads, 64 samples per CTA.
// ---------------------------------------------------------------------------
__global__ void __launch_bounds__(512, 1)
lstm_kernel(const float* __restrict__ enc_b, const float* __restrict__ dec_b,
            const float* __restrict__ dense_W, const float* __restrict__ dense_b,
            float* __restrict__ out)
{
    extern __shared__ float smem[];
    float* hA  = smem;
    float* hB  = smem + HBUF;
    float* cs  = smem + 2 * HBUF;
    float* xsA = smem + 3 * HBUF;
    float* xsB = xsA + C_IN * 64;

    const int tid = threadIdx.x;
    const int k_h = tid & 255;
    const int nh  = tid >> 8;          // 0 or 1: sample half
    const int n0  = blockIdx.x * 64;

    // zero h (current) and c; hB is fully overwritten before first read
    for (int i = tid; i < HBUF; i += 512) { hA[i] = 0.0f; cs[i] = 0.0f; }
    // preload x tile for t=0
    for (int i = tid; i < C_IN * 64; i += 512)
        xsA[i] = g_xT[(i >> 6) * NBATCH + n0 + (i & 63)];
    __syncthreads();

    float* hcur = hA;
    float* hnxt = hB;

    // -------- encoder --------
    {
        ULL bi = dup2(enc_b[k_h]),       bf = dup2(enc_b[256 + k_h]);
        ULL bg = dup2(enc_b[512 + k_h]), bo = dup2(enc_b[768 + k_h]);
        for (int t = 0; t < T_IN; ++t) {
            lstm_pass<true>(g_WhhTe2, bi, bf, bg, bo, hcur, hnxt, cs, xsA,
                            k_h, nh * 32);
            lstm_pass<true>(g_WhhTe2, bi, bf, bg, bo, hcur, hnxt, cs, xsA,
                            k_h, nh * 32 + 16);
            if (t + 1 < T_IN) {
                for (int i = tid; i < C_IN * 64; i += 512)
                    xsB[i] = g_xT[((t + 1) * C_IN + (i >> 6)) * NBATCH
                                  + n0 + (i & 63)];
            }
            __syncthreads();
            float* tp = hcur; hcur = hnxt; hnxt = tp;
            tp = xsA; xsA = xsB; xsB = tp;
        }
    }

    // decoder starts from (h_enc, c = 0)
    for (int i = tid; i < HBUF; i += 512) cs[i] = 0.0f;
    __syncthreads();

    // -------- decoder + per-timestep dense --------
    const int nl = tid & 63;
    const int oo = tid >> 6;           // 0..7
    {
        ULL bi = dup2(dec_b[k_h]),       bf = dup2(dec_b[256 + k_h]);
        ULL bg = dup2(dec_b[512 + k_h]), bo = dup2(dec_b[768 + k_h]);
        for (int t = 0; t < T_OUT; ++t) {
            lstm_pass<false>(g_WhhTd2, bi, bf, bg, bo, hcur, hnxt, cs, nullptr,
                             k_h, nh * 32);
            lstm_pass<false>(g_WhhTd2, bi, bf, bg, bo, hcur, hnxt, cs, nullptr,
                             k_h, nh * 32 + 16);
            __syncthreads();
            float* tp = hcur; hcur = hnxt; hnxt = tp;

            // dense: out[n][o][t] = b[t][o] + sum_k h[n][k] * W[t][o][k]
            // dw is warp-uniform (broadcast LDG.128); hr is conflict-free LDS.
            const float4* dw = reinterpret_cast<const float4*>(
                dense_W + (t * C_OUT + oo) * HID);
            const float* hr = hcur + nl;
            float a = __ldg(dense_b + t * C_OUT + oo);
            #pragma unroll 4
            for (int k4 = 0; k4 < HID / 4; ++k4) {
                float4 w = __ldg(dw + k4);
                a = fmaf(hr[(4 * k4 + 0) * HS], w.x, a);
                a = fmaf(hr[(4 * k4 + 1) * HS], w.y, a);
                a = fmaf(hr[(4 * k4 + 2) * HS], w.z, a);
                a = fmaf(hr[(4 * k4 + 3) * HS], w.w, a);
            }
            out[((size_t)(n0 + nl) * C_OUT + oo) * T_OUT + t] = a;
            // no sync needed: next step writes the other h buffer; this one is
            // only rewritten after the next step's end-of-step barrier.
        }
    }
}

#undef FMA8

// ---------------------------------------------------------------------------
extern "C" void kernel_launch(void* const* d_in, const int* in_sizes, int n_in,
                              void* d_out, int out_size)
{
    (void)in_sizes; (void)n_in; (void)out_size;
    const float* x        = (const float*)d_in[0];
    const float* enc_Wih  = (const float*)d_in[1];
    const float* enc_Whh  = (const float*)d_in[2];
    const float* enc_b    = (const float*)d_in[3];
    const float* dec_Whh  = (const float*)d_in[4];
    const float* dec_b    = (const float*)d_in[5];
    const float* dense_W  = (const float*)d_in[6];
    const float* dense_b  = (const float*)d_in[7];
    float* out = (float*)d_out;

    cudaFuncSetAttribute(lstm_kernel,
                         cudaFuncAttributeMaxDynamicSharedMemorySize, SMEM_BYTES);

    prep_kernel<<<1024, 512>>>(x, enc_Wih, enc_Whh, dec_Whh);
    lstm_kernel<<<128, 512, SMEM_BYTES>>>(enc_b, dec_b, dense_W, dense_b, out);
}